// round 8
// baseline (speedup 1.0000x reference)
#include <cuda_runtime.h>
#include <cuda_fp16.h>
#include <cstdint>

// Problem constants
#define T_TOK 4096
#define H_DIM 1024
#define F_DIM 4096
#define N_EXP 8

// Tiling: CTA 128m x 256n x 32k, 8 warps (2m x 4n), warp tile 64x64, fp16 MMA
#define NT 256
#define KC 32
#define NSTAGE 8
#define A_STAGE_BYTES (128 * 64)          // 128 rows x 32 halves (64B)
#define B_STAGE_BYTES (KC * NT * 2)       // 32 k-rows x 512B
#define STAGE_STRIDE  (A_STAGE_BYTES + B_STAGE_BYTES)   // 24KB
#define SMEM_TILES_OFF 1024
#define SMEM_BYTES (SMEM_TILES_OFF + NSTAGE * STAGE_STRIDE)   // 197632

// -------- device scratch --------
__device__ int    g_cnt[N_EXP];
__device__ int    g_list[N_EXP][T_TOK];
__device__ float  g_wt[N_EXP][T_TOK];
__device__ __half g_xh[(size_t)T_TOK * H_DIM];
__device__ __half g_w1h[(size_t)N_EXP * H_DIM * F_DIM];
__device__ __half g_w2h[(size_t)N_EXP * F_DIM * H_DIM];
__device__ __half g_h[(size_t)N_EXP * T_TOK * F_DIM];

// -------- helpers --------
__device__ __forceinline__ uint32_t smem_u32(const void* p) {
    uint32_t a;
    asm("{ .reg .u64 t; cvta.to.shared.u64 t, %1; cvt.u32.u64 %0, t; }" : "=r"(a) : "l"(p));
    return a;
}
__device__ __forceinline__ void cp16(uint32_t dst, const void* src) {
    asm volatile("cp.async.cg.shared.global [%0], [%1], 16;" :: "r"(dst), "l"(src) : "memory");
}
#define CP_COMMIT() asm volatile("cp.async.commit_group;" ::: "memory")

__device__ __forceinline__ void mma_f16(float c[4], const uint32_t a[4],
                                        uint32_t b0, uint32_t b1) {
    asm volatile(
        "mma.sync.aligned.m16n8k16.row.col.f32.f16.f16.f32 "
        "{%0,%1,%2,%3}, {%4,%5,%6,%7}, {%8,%9}, {%0,%1,%2,%3};"
        : "+f"(c[0]), "+f"(c[1]), "+f"(c[2]), "+f"(c[3])
        : "r"(a[0]), "r"(a[1]), "r"(a[2]), "r"(a[3]), "r"(b0), "r"(b1));
}
#define LDM_X4(r0, r1, r2, r3, addr) \
    asm volatile("ldmatrix.sync.aligned.m8n8.x4.shared.b16 {%0,%1,%2,%3}, [%4];" \
                 : "=r"(r0), "=r"(r1), "=r"(r2), "=r"(r3) : "r"(addr))
#define LDM_X4T(r0, r1, r2, r3, addr) \
    asm volatile("ldmatrix.sync.aligned.m8n8.x4.trans.shared.b16 {%0,%1,%2,%3}, [%4];" \
                 : "=r"(r0), "=r"(r1), "=r"(r2), "=r"(r3) : "r"(addr))

__device__ __forceinline__ float gelu_exact(float x) {
    return 0.5f * x * (1.0f + erff(x * 0.70710678118654752f));
}

// ------------------------------ convert kernel -----------------------------
__global__ void cvt_kernel(const float4* __restrict__ src, __half2* __restrict__ dst,
                           int n4) {
    int i = blockIdx.x * blockDim.x + threadIdx.x;
    if (i < n4) {
        float4 v = src[i];
        dst[2 * i]     = __floats2half2_rn(v.x, v.y);
        dst[2 * i + 1] = __floats2half2_rn(v.z, v.w);
    }
}

// ------------------------------ zero kernel --------------------------------
__global__ void zero_kernel(float* __restrict__ out) {
    int i = blockIdx.x * blockDim.x + threadIdx.x;
    if (i < T_TOK * H_DIM) out[i] = 0.0f;
    if (i < N_EXP) g_cnt[i] = 0;
}

// ------------------------------ router kernel ------------------------------
__global__ void router_kernel(const float* __restrict__ x,
                              const float* __restrict__ rw,
                              const float* __restrict__ rb) {
    int gwarp = (blockIdx.x * blockDim.x + threadIdx.x) >> 5;
    if (gwarp >= T_TOK) return;
    int lane = threadIdx.x & 31;
    const float* xr = x + (size_t)gwarp * H_DIM;
    float p[N_EXP];
#pragma unroll
    for (int e = 0; e < N_EXP; e++) p[e] = 0.0f;
    for (int i = lane; i < H_DIM; i += 32) {
        float xv = xr[i];
        const float4* r4 = (const float4*)(rw + i * N_EXP);
        float4 ra = r4[0], rc = r4[1];
        p[0] += xv * ra.x; p[1] += xv * ra.y; p[2] += xv * ra.z; p[3] += xv * ra.w;
        p[4] += xv * rc.x; p[5] += xv * rc.y; p[6] += xv * rc.z; p[7] += xv * rc.w;
    }
#pragma unroll
    for (int e = 0; e < N_EXP; e++) {
#pragma unroll
        for (int o = 16; o > 0; o >>= 1) p[e] += __shfl_xor_sync(0xffffffffu, p[e], o);
    }
    if (lane == 0) {
#pragma unroll
        for (int e = 0; e < N_EXP; e++) p[e] += rb[e];
        int i1 = 0;
#pragma unroll
        for (int e = 1; e < N_EXP; e++) if (p[e] > p[i1]) i1 = e;
        int i2 = (i1 == 0) ? 1 : 0;
#pragma unroll
        for (int e = 0; e < N_EXP; e++) if (e != i1 && p[e] > p[i2]) i2 = e;
        float wa = 1.0f / (1.0f + expf(p[i2] - p[i1]));
        float wb = 1.0f - wa;
        int p1 = atomicAdd(&g_cnt[i1], 1);
        g_list[i1][p1] = gwarp; g_wt[i1][p1] = wa;
        int p2 = atomicAdd(&g_cnt[i2], 1);
        g_list[i2][p2] = gwarp; g_wt[i2][p2] = wb;
    }
}

// --------------------------- grouped GEMM kernel ---------------------------
// A smem: [m(128)][k(32)] fp16, 64B rows, unit swizzle u^=(row&3).
// B smem: [k(32)][n(256)] fp16, 512B rows, unit swizzle u^=(k&7).
// KSPLIT: GEMM2 splits K across blockIdx.z (atomicAdd accumulates; bias on slice 0).
template <int KDIM, int NDIM, int PHASE, int KSPLIT>
__global__ void __launch_bounds__(256)
moe_gemm(const __half* __restrict__ Ah,
         const __half* __restrict__ Wh,
         const float* __restrict__ bias,
         float* __restrict__ out) {
    extern __shared__ char smem[];
    const int e   = blockIdx.z / KSPLIT;
    const int kz  = blockIdx.z % KSPLIT;
    const int cnt = g_cnt[e];
    const int m0  = blockIdx.x * 128;
    if (m0 >= cnt) return;
    const int n0  = blockIdx.y * NT;
    constexpr int KLEN = KDIM / KSPLIT;
    const int kbase = kz * KLEN;

    const int tid  = threadIdx.x;
    const int lane = tid & 31;
    const int warp = tid >> 5;
    const int wm   = (warp & 1) * 64;
    const int wn   = (warp >> 1) * 64;
    const int grp  = lane >> 2;
    const int tig  = lane & 3;

    int*   sTok = (int*)(smem);          // [128]
    float* sWt  = (float*)(smem + 512);  // [128]

    if (tid < 128) {
        int mc = min(m0 + tid, cnt - 1);
        sTok[tid] = g_list[e][mc];
        sWt[tid]  = g_wt[e][mc];
    }
    __syncthreads();

    const __half* Aexp = (PHASE == 1) ? Ah : (g_h + (size_t)e * T_TOK * F_DIM);
    const __half* Wexp = Wh + (size_t)e * KDIM * NDIM;
    constexpr int NC = KLEN / KC;
    const uint32_t sb = smem_u32(smem) + SMEM_TILES_OFF;

    auto issue = [&](int c) {
        const uint32_t aB = sb + (c % NSTAGE) * STAGE_STRIDE;
        const uint32_t bB = aB + A_STAGE_BYTES;
        const int k0 = kbase + c * KC;
        // A tile: 512 16B-chunks, 2 per thread
#pragma unroll
        for (int i = 0; i < 2; i++) {
            int idx = tid + i * 256;
            int r   = idx >> 2;
            int u   = idx & 3;
            const __half* src;
            if (PHASE == 1) src = Ah + (size_t)sTok[r] * KDIM + k0 + u * 8;
            else            src = Aexp + (size_t)min(m0 + r, cnt - 1) * KDIM + k0 + u * 8;
            cp16(aB + (uint32_t)(r * 64 + ((u ^ (r & 3)) << 4)), src);
        }
        // B tile: 1024 16B-chunks, 4 per thread
#pragma unroll
        for (int i = 0; i < 4; i++) {
            int idx = tid + i * 256;
            int k   = idx >> 5;
            int u   = idx & 31;
            const __half* src = Wexp + (size_t)(k0 + k) * NDIM + n0 + u * 8;
            cp16(bB + (uint32_t)(k * 512 + ((u ^ (k & 7)) << 4)), src);
        }
        CP_COMMIT();
    };

    float acc[4][8][4];
#pragma unroll
    for (int mi = 0; mi < 4; mi++)
#pragma unroll
        for (int ni = 0; ni < 8; ni++)
#pragma unroll
            for (int q = 0; q < 4; q++) acc[mi][ni][q] = 0.0f;

    // per-lane ldmatrix coordinates
    const int l7 = lane & 7;
    const int lh = (lane >> 3) & 1;
    const int lu = lane >> 4;
    int aRow[4], aRx[4];
#pragma unroll
    for (int mi = 0; mi < 4; mi++) {
        int row = wm + mi * 16 + l7 + lh * 8;
        aRow[mi] = row * 64;
        aRx[mi]  = row & 3;
    }
    const int bUbase = (wn >> 3) + lu;

    // pipeline: prefetch depth NSTAGE-2; compute c = cc - (NSTAGE-2) for c in [0, NC)
#pragma unroll 1
    for (int cc = 0; cc < NC + NSTAGE - 2; cc++) {
        if (cc < NC) { issue(cc); } else { CP_COMMIT(); }
        if (cc < NSTAGE - 2) continue;
        const int c = cc - (NSTAGE - 2);
        asm volatile("cp.async.wait_group %0;" :: "n"(NSTAGE - 2) : "memory");
        __syncthreads();

        const uint32_t aB = sb + (c % NSTAGE) * STAGE_STRIDE;
        const uint32_t bB = aB + A_STAGE_BYTES;
#pragma unroll
        for (int ks = 0; ks < 2; ks++) {
            const int kl = ks * 16 + l7 + lh * 8;   // B k-row for this lane
            const uint32_t bkBase = bB + (uint32_t)(kl * 512);
            const int kx = kl & 7;
            uint32_t b0[8], b1[8];
#pragma unroll
            for (int pr = 0; pr < 4; pr++) {
                uint32_t addr = bkBase + (uint32_t)(((bUbase + pr * 2) ^ kx) << 4);
                LDM_X4T(b0[pr * 2], b1[pr * 2], b0[pr * 2 + 1], b1[pr * 2 + 1], addr);
            }
            uint32_t a[4][4];
#pragma unroll
            for (int mi = 0; mi < 4; mi++) {
                uint32_t addr = aB + (uint32_t)(aRow[mi] + (((ks * 2 + lu) ^ aRx[mi]) << 4));
                LDM_X4(a[mi][0], a[mi][1], a[mi][2], a[mi][3], addr);
            }
#pragma unroll
            for (int mi = 0; mi < 4; mi++)
#pragma unroll
                for (int ni = 0; ni < 8; ni++)
                    mma_f16(acc[mi][ni], a[mi], b0[ni], b1[ni]);
        }
    }
    asm volatile("cp.async.wait_group 0;" ::: "memory");

    // ------------------------------ epilogue ------------------------------
#pragma unroll
    for (int mi = 0; mi < 4; mi++) {
#pragma unroll
        for (int ni = 0; ni < 8; ni++) {
            int gn = n0 + wn + ni * 8 + tig * 2;
            float bv0 = 0.0f, bv1 = 0.0f;
            if (kz == 0) {
                bv0 = bias[(size_t)e * NDIM + gn];
                bv1 = bias[(size_t)e * NDIM + gn + 1];
            }
#pragma unroll
            for (int half = 0; half < 2; half++) {
                int r = m0 + wm + mi * 16 + grp + half * 8;
                if (r < cnt) {
                    float v0 = acc[mi][ni][half * 2 + 0] + bv0;
                    float v1 = acc[mi][ni][half * 2 + 1] + bv1;
                    if (PHASE == 1) {
                        __half2* dst = (__half2*)(g_h + (size_t)e * T_TOK * F_DIM +
                                                  (size_t)r * F_DIM + gn);
                        *dst = __floats2half2_rn(gelu_exact(v0), gelu_exact(v1));
                    } else {
                        int   tok = sTok[r - m0];
                        float wt  = sWt[r - m0];
                        atomicAdd(&out[(size_t)tok * H_DIM + gn],     wt * v0);
                        atomicAdd(&out[(size_t)tok * H_DIM + gn + 1], wt * v1);
                    }
                }
            }
        }
    }
}

// ------------------------------ launch ------------------------------------
extern "C" void kernel_launch(void* const* d_in, const int* in_sizes, int n_in,
                              void* d_out, int out_size) {
    const float* x  = (const float*)d_in[0];
    const float* rw = (const float*)d_in[1];
    const float* rb = (const float*)d_in[2];
    const float* w1 = (const float*)d_in[3];
    const float* b1 = (const float*)d_in[4];
    const float* w2 = (const float*)d_in[5];
    const float* b2 = (const float*)d_in[6];
    float* out = (float*)d_out;

    cudaFuncSetAttribute(moe_gemm<H_DIM, F_DIM, 1, 1>,
                         cudaFuncAttributeMaxDynamicSharedMemorySize, SMEM_BYTES);
    cudaFuncSetAttribute(moe_gemm<F_DIM, H_DIM, 2, 2>,
                         cudaFuncAttributeMaxDynamicSharedMemorySize, SMEM_BYTES);

    __half *p_xh, *p_w1h, *p_w2h;
    cudaGetSymbolAddress((void**)&p_xh,  g_xh);
    cudaGetSymbolAddress((void**)&p_w1h, g_w1h);
    cudaGetSymbolAddress((void**)&p_w2h, g_w2h);

    const int n4_x  = T_TOK * H_DIM / 4;
    const int n4_w1 = N_EXP * H_DIM * F_DIM / 4;
    const int n4_w2 = N_EXP * F_DIM * H_DIM / 4;

    zero_kernel<<<(T_TOK * H_DIM + 255) / 256, 256>>>(out);
    cvt_kernel<<<(n4_x + 255) / 256, 256>>>((const float4*)x, (__half2*)p_xh, n4_x);
    cvt_kernel<<<(n4_w1 + 255) / 256, 256>>>((const float4*)w1, (__half2*)p_w1h, n4_w1);
    cvt_kernel<<<(n4_w2 + 255) / 256, 256>>>((const float4*)w2, (__half2*)p_w2h, n4_w2);
    router_kernel<<<(T_TOK * 32 + 255) / 256, 256>>>(x, rw, rb);
    moe_gemm<H_DIM, F_DIM, 1, 1>
        <<<dim3(T_TOK / 128, F_DIM / NT, N_EXP), 256, SMEM_BYTES>>>(p_xh, p_w1h, b1, nullptr);
    moe_gemm<F_DIM, H_DIM, 2, 2>
        <<<dim3(T_TOK / 128, H_DIM / NT, N_EXP * 2), 256, SMEM_BYTES>>>(nullptr, p_w2h, b2, out);
}

// round 9
// speedup vs baseline: 1.0186x; 1.0186x over previous
#include <cuda_runtime.h>
#include <cuda_fp16.h>
#include <cstdint>

// Problem constants
#define T_TOK 4096
#define H_DIM 1024
#define F_DIM 4096
#define N_EXP 8

// Tiling: CTA 128m x 256n x 32k, 8 warps (2m x 4n), warp tile 64x64, fp16 MMA
#define NT 256
#define KC 32
#define NSTAGE 4
#define A_STAGE_BYTES (128 * 64)          // 128 rows x 32 halves (64B)
#define B_STAGE_BYTES (KC * NT * 2)       // 32 k-rows x 512B
#define STAGE_STRIDE  (A_STAGE_BYTES + B_STAGE_BYTES)   // 24KB
#define SMEM_TILES_OFF 1024
#define SMEM_BYTES (SMEM_TILES_OFF + NSTAGE * STAGE_STRIDE)   // 99328 -> 2 CTAs/SM

// -------- device scratch --------
__device__ int    g_cnt[N_EXP];
__device__ int    g_list[N_EXP][T_TOK];
__device__ float  g_wt[N_EXP][T_TOK];
__device__ __half g_xh[(size_t)T_TOK * H_DIM];
__device__ __half g_w1h[(size_t)N_EXP * H_DIM * F_DIM];
__device__ __half g_w2h[(size_t)N_EXP * F_DIM * H_DIM];
__device__ __half g_h[(size_t)N_EXP * T_TOK * F_DIM];

// -------- helpers --------
__device__ __forceinline__ uint32_t smem_u32(const void* p) {
    uint32_t a;
    asm("{ .reg .u64 t; cvta.to.shared.u64 t, %1; cvt.u32.u64 %0, t; }" : "=r"(a) : "l"(p));
    return a;
}
__device__ __forceinline__ void cp16(uint32_t dst, const void* src) {
    asm volatile("cp.async.cg.shared.global [%0], [%1], 16;" :: "r"(dst), "l"(src) : "memory");
}
#define CP_COMMIT() asm volatile("cp.async.commit_group;" ::: "memory")

__device__ __forceinline__ void mma_f16(float c[4], const uint32_t a[4],
                                        uint32_t b0, uint32_t b1) {
    asm volatile(
        "mma.sync.aligned.m16n8k16.row.col.f32.f16.f16.f32 "
        "{%0,%1,%2,%3}, {%4,%5,%6,%7}, {%8,%9}, {%0,%1,%2,%3};"
        : "+f"(c[0]), "+f"(c[1]), "+f"(c[2]), "+f"(c[3])
        : "r"(a[0]), "r"(a[1]), "r"(a[2]), "r"(a[3]), "r"(b0), "r"(b1));
}
#define LDM_X4(r0, r1, r2, r3, addr) \
    asm volatile("ldmatrix.sync.aligned.m8n8.x4.shared.b16 {%0,%1,%2,%3}, [%4];" \
                 : "=r"(r0), "=r"(r1), "=r"(r2), "=r"(r3) : "r"(addr))
#define LDM_X4T(r0, r1, r2, r3, addr) \
    asm volatile("ldmatrix.sync.aligned.m8n8.x4.trans.shared.b16 {%0,%1,%2,%3}, [%4];" \
                 : "=r"(r0), "=r"(r1), "=r"(r2), "=r"(r3) : "r"(addr))

__device__ __forceinline__ float gelu_exact(float x) {
    return 0.5f * x * (1.0f + erff(x * 0.70710678118654752f));
}

// ------------------------------ convert kernel -----------------------------
__global__ void cvt_kernel(const float4* __restrict__ src, __half2* __restrict__ dst,
                           int n4) {
    int i = blockIdx.x * blockDim.x + threadIdx.x;
    if (i < n4) {
        float4 v = src[i];
        dst[2 * i]     = __floats2half2_rn(v.x, v.y);
        dst[2 * i + 1] = __floats2half2_rn(v.z, v.w);
    }
}

// ------------------------------ zero kernel --------------------------------
__global__ void zero_kernel(float* __restrict__ out) {
    int i = blockIdx.x * blockDim.x + threadIdx.x;
    if (i < T_TOK * H_DIM) out[i] = 0.0f;
    if (i < N_EXP) g_cnt[i] = 0;
}

// ------------------------------ router kernel ------------------------------
__global__ void router_kernel(const float* __restrict__ x,
                              const float* __restrict__ rw,
                              const float* __restrict__ rb) {
    int gwarp = (blockIdx.x * blockDim.x + threadIdx.x) >> 5;
    if (gwarp >= T_TOK) return;
    int lane = threadIdx.x & 31;
    const float* xr = x + (size_t)gwarp * H_DIM;
    float p[N_EXP];
#pragma unroll
    for (int e = 0; e < N_EXP; e++) p[e] = 0.0f;
    for (int i = lane; i < H_DIM; i += 32) {
        float xv = xr[i];
        const float4* r4 = (const float4*)(rw + i * N_EXP);
        float4 ra = r4[0], rc = r4[1];
        p[0] += xv * ra.x; p[1] += xv * ra.y; p[2] += xv * ra.z; p[3] += xv * ra.w;
        p[4] += xv * rc.x; p[5] += xv * rc.y; p[6] += xv * rc.z; p[7] += xv * rc.w;
    }
#pragma unroll
    for (int e = 0; e < N_EXP; e++) {
#pragma unroll
        for (int o = 16; o > 0; o >>= 1) p[e] += __shfl_xor_sync(0xffffffffu, p[e], o);
    }
    if (lane == 0) {
#pragma unroll
        for (int e = 0; e < N_EXP; e++) p[e] += rb[e];
        int i1 = 0;
#pragma unroll
        for (int e = 1; e < N_EXP; e++) if (p[e] > p[i1]) i1 = e;
        int i2 = (i1 == 0) ? 1 : 0;
#pragma unroll
        for (int e = 0; e < N_EXP; e++) if (e != i1 && p[e] > p[i2]) i2 = e;
        float wa = 1.0f / (1.0f + expf(p[i2] - p[i1]));
        float wb = 1.0f - wa;
        int p1 = atomicAdd(&g_cnt[i1], 1);
        g_list[i1][p1] = gwarp; g_wt[i1][p1] = wa;
        int p2 = atomicAdd(&g_cnt[i2], 1);
        g_list[i2][p2] = gwarp; g_wt[i2][p2] = wb;
    }
}

// --------------------------- grouped GEMM kernel ---------------------------
// A smem: [m(128)][k(32)] fp16, 64B rows, unit swizzle u^=(row&3).
// B smem: [k(32)][n(256)] fp16, 512B rows, unit swizzle u^=(k&7).
template <int KDIM, int NDIM, int PHASE>
__global__ void __launch_bounds__(256)
moe_gemm(const __half* __restrict__ Ah,
         const __half* __restrict__ Wh,
         const float* __restrict__ bias,
         float* __restrict__ out) {
    extern __shared__ char smem[];
    const int e   = blockIdx.z;
    const int cnt = g_cnt[e];
    const int m0  = blockIdx.x * 128;
    if (m0 >= cnt) return;
    const int n0  = blockIdx.y * NT;

    const int tid  = threadIdx.x;
    const int lane = tid & 31;
    const int warp = tid >> 5;
    const int wm   = (warp & 1) * 64;
    const int wn   = (warp >> 1) * 64;
    const int grp  = lane >> 2;
    const int tig  = lane & 3;

    int*   sTok = (int*)(smem);          // [128]
    float* sWt  = (float*)(smem + 512);  // [128]

    if (tid < 128) {
        int mc = min(m0 + tid, cnt - 1);
        sTok[tid] = g_list[e][mc];
        sWt[tid]  = g_wt[e][mc];
    }
    __syncthreads();

    const __half* Aexp = (PHASE == 1) ? Ah : (g_h + (size_t)e * T_TOK * F_DIM);
    const __half* Wexp = Wh + (size_t)e * KDIM * NDIM;
    constexpr int NC = KDIM / KC;
    const uint32_t sb = smem_u32(smem) + SMEM_TILES_OFF;

    auto issue = [&](int c) {
        const uint32_t aB = sb + (c % NSTAGE) * STAGE_STRIDE;
        const uint32_t bB = aB + A_STAGE_BYTES;
        const int k0 = c * KC;
        // A tile: 512 16B-chunks, 2 per thread
#pragma unroll
        for (int i = 0; i < 2; i++) {
            int idx = tid + i * 256;
            int r   = idx >> 2;
            int u   = idx & 3;
            const __half* src;
            if (PHASE == 1) src = Ah + (size_t)sTok[r] * KDIM + k0 + u * 8;
            else            src = Aexp + (size_t)min(m0 + r, cnt - 1) * KDIM + k0 + u * 8;
            cp16(aB + (uint32_t)(r * 64 + ((u ^ (r & 3)) << 4)), src);
        }
        // B tile: 1024 16B-chunks, 4 per thread
#pragma unroll
        for (int i = 0; i < 4; i++) {
            int idx = tid + i * 256;
            int k   = idx >> 5;
            int u   = idx & 31;
            const __half* src = Wexp + (size_t)(k0 + k) * NDIM + n0 + u * 8;
            cp16(bB + (uint32_t)(k * 512 + ((u ^ (k & 7)) << 4)), src);
        }
        CP_COMMIT();
    };

    float acc[4][8][4];
#pragma unroll
    for (int mi = 0; mi < 4; mi++)
#pragma unroll
        for (int ni = 0; ni < 8; ni++)
#pragma unroll
            for (int q = 0; q < 4; q++) acc[mi][ni][q] = 0.0f;

    // per-lane ldmatrix coordinates
    const int l7 = lane & 7;
    const int lh = (lane >> 3) & 1;
    const int lu = lane >> 4;
    int aRow[4], aRx[4];
#pragma unroll
    for (int mi = 0; mi < 4; mi++) {
        int row = wm + mi * 16 + l7 + lh * 8;
        aRow[mi] = row * 64;
        aRx[mi]  = row & 3;
    }
    const int bUbase = (wn >> 3) + lu;

    // pipeline: prefetch depth NSTAGE-2; compute c = cc - (NSTAGE-2) for c in [0, NC)
#pragma unroll 1
    for (int cc = 0; cc < NC + NSTAGE - 2; cc++) {
        if (cc < NC) { issue(cc); } else { CP_COMMIT(); }
        if (cc < NSTAGE - 2) continue;
        const int c = cc - (NSTAGE - 2);
        asm volatile("cp.async.wait_group %0;" :: "n"(NSTAGE - 2) : "memory");
        __syncthreads();

        const uint32_t aB = sb + (c % NSTAGE) * STAGE_STRIDE;
        const uint32_t bB = aB + A_STAGE_BYTES;
#pragma unroll
        for (int ks = 0; ks < 2; ks++) {
            const int kl = ks * 16 + l7 + lh * 8;   // B k-row for this lane
            const uint32_t bkBase = bB + (uint32_t)(kl * 512);
            const int kx = kl & 7;
            uint32_t b0[8], b1[8];
#pragma unroll
            for (int pr = 0; pr < 4; pr++) {
                uint32_t addr = bkBase + (uint32_t)(((bUbase + pr * 2) ^ kx) << 4);
                LDM_X4T(b0[pr * 2], b1[pr * 2], b0[pr * 2 + 1], b1[pr * 2 + 1], addr);
            }
            uint32_t a[4][4];
#pragma unroll
            for (int mi = 0; mi < 4; mi++) {
                uint32_t addr = aB + (uint32_t)(aRow[mi] + (((ks * 2 + lu) ^ aRx[mi]) << 4));
                LDM_X4(a[mi][0], a[mi][1], a[mi][2], a[mi][3], addr);
            }
#pragma unroll
            for (int mi = 0; mi < 4; mi++)
#pragma unroll
                for (int ni = 0; ni < 8; ni++)
                    mma_f16(acc[mi][ni], a[mi], b0[ni], b1[ni]);
        }
    }
    asm volatile("cp.async.wait_group 0;" ::: "memory");

    // ------------------------------ epilogue ------------------------------
#pragma unroll
    for (int mi = 0; mi < 4; mi++) {
#pragma unroll
        for (int ni = 0; ni < 8; ni++) {
            int gn = n0 + wn + ni * 8 + tig * 2;
            float bv0 = bias[(size_t)e * NDIM + gn];
            float bv1 = bias[(size_t)e * NDIM + gn + 1];
#pragma unroll
            for (int half = 0; half < 2; half++) {
                int r = m0 + wm + mi * 16 + grp + half * 8;
                if (r < cnt) {
                    float v0 = acc[mi][ni][half * 2 + 0] + bv0;
                    float v1 = acc[mi][ni][half * 2 + 1] + bv1;
                    if (PHASE == 1) {
                        __half2* dst = (__half2*)(g_h + (size_t)e * T_TOK * F_DIM +
                                                  (size_t)r * F_DIM + gn);
                        *dst = __floats2half2_rn(gelu_exact(v0), gelu_exact(v1));
                    } else {
                        int   tok = sTok[r - m0];
                        float wt  = sWt[r - m0];
                        atomicAdd(&out[(size_t)tok * H_DIM + gn],     wt * v0);
                        atomicAdd(&out[(size_t)tok * H_DIM + gn + 1], wt * v1);
                    }
                }
            }
        }
    }
}

// ------------------------------ launch ------------------------------------
extern "C" void kernel_launch(void* const* d_in, const int* in_sizes, int n_in,
                              void* d_out, int out_size) {
    const float* x  = (const float*)d_in[0];
    const float* rw = (const float*)d_in[1];
    const float* rb = (const float*)d_in[2];
    const float* w1 = (const float*)d_in[3];
    const float* b1 = (const float*)d_in[4];
    const float* w2 = (const float*)d_in[5];
    const float* b2 = (const float*)d_in[6];
    float* out = (float*)d_out;

    cudaFuncSetAttribute(moe_gemm<H_DIM, F_DIM, 1>,
                         cudaFuncAttributeMaxDynamicSharedMemorySize, SMEM_BYTES);
    cudaFuncSetAttribute(moe_gemm<F_DIM, H_DIM, 2>,
                         cudaFuncAttributeMaxDynamicSharedMemorySize, SMEM_BYTES);

    __half *p_xh, *p_w1h, *p_w2h;
    cudaGetSymbolAddress((void**)&p_xh,  g_xh);
    cudaGetSymbolAddress((void**)&p_w1h, g_w1h);
    cudaGetSymbolAddress((void**)&p_w2h, g_w2h);

    const int n4_x  = T_TOK * H_DIM / 4;
    const int n4_w1 = N_EXP * H_DIM * F_DIM / 4;
    const int n4_w2 = N_EXP * F_DIM * H_DIM / 4;

    zero_kernel<<<(T_TOK * H_DIM + 255) / 256, 256>>>(out);
    cvt_kernel<<<(n4_x + 255) / 256, 256>>>((const float4*)x, (__half2*)p_xh, n4_x);
    cvt_kernel<<<(n4_w1 + 255) / 256, 256>>>((const float4*)w1, (__half2*)p_w1h, n4_w1);
    cvt_kernel<<<(n4_w2 + 255) / 256, 256>>>((const float4*)w2, (__half2*)p_w2h, n4_w2);
    router_kernel<<<(T_TOK * 32 + 255) / 256, 256>>>(x, rw, rb);
    moe_gemm<H_DIM, F_DIM, 1>
        <<<dim3(T_TOK / 128, F_DIM / NT, N_EXP), 256, SMEM_BYTES>>>(p_xh, p_w1h, b1, nullptr);
    moe_gemm<F_DIM, H_DIM, 2>
        <<<dim3(T_TOK / 128, H_DIM / NT, N_EXP), 256, SMEM_BYTES>>>(nullptr, p_w2h, b2, out);
}

// round 10
// speedup vs baseline: 1.0346x; 1.0157x over previous
#include <cuda_runtime.h>
#include <cuda_fp16.h>
#include <cstdint>

// Problem constants
#define T_TOK 4096
#define H_DIM 1024
#define F_DIM 4096
#define N_EXP 8

// Tiling: CTA 128m x 256n x 32k, 16 warps (4m x 4n), warp tile 32x64, fp16 MMA
#define NT 256
#define KC 32
#define NTHREADS 512
#define NSTAGE 4
#define A_STAGE_BYTES (128 * 64)          // 128 rows x 32 halves (64B)
#define B_STAGE_BYTES (KC * NT * 2)       // 32 k-rows x 512B
#define STAGE_STRIDE  (A_STAGE_BYTES + B_STAGE_BYTES)   // 24KB
#define SMEM_TILES_OFF 1024
#define SMEM_BYTES (SMEM_TILES_OFF + NSTAGE * STAGE_STRIDE)   // 99328

// -------- device scratch --------
__device__ int    g_cnt[N_EXP];
__device__ int    g_list[N_EXP][T_TOK];
__device__ float  g_wt[N_EXP][T_TOK];
__device__ __half g_xh[(size_t)T_TOK * H_DIM];
__device__ __half g_w1h[(size_t)N_EXP * H_DIM * F_DIM];
__device__ __half g_w2h[(size_t)N_EXP * F_DIM * H_DIM];
__device__ __half g_h[(size_t)N_EXP * T_TOK * F_DIM];

// -------- helpers --------
__device__ __forceinline__ uint32_t smem_u32(const void* p) {
    uint32_t a;
    asm("{ .reg .u64 t; cvta.to.shared.u64 t, %1; cvt.u32.u64 %0, t; }" : "=r"(a) : "l"(p));
    return a;
}
__device__ __forceinline__ void cp16(uint32_t dst, const void* src) {
    asm volatile("cp.async.cg.shared.global [%0], [%1], 16;" :: "r"(dst), "l"(src) : "memory");
}
#define CP_COMMIT() asm volatile("cp.async.commit_group;" ::: "memory")

__device__ __forceinline__ void mma_f16(float c[4], const uint32_t a[4],
                                        uint32_t b0, uint32_t b1) {
    asm volatile(
        "mma.sync.aligned.m16n8k16.row.col.f32.f16.f16.f32 "
        "{%0,%1,%2,%3}, {%4,%5,%6,%7}, {%8,%9}, {%0,%1,%2,%3};"
        : "+f"(c[0]), "+f"(c[1]), "+f"(c[2]), "+f"(c[3])
        : "r"(a[0]), "r"(a[1]), "r"(a[2]), "r"(a[3]), "r"(b0), "r"(b1));
}
#define LDM_X4(r0, r1, r2, r3, addr) \
    asm volatile("ldmatrix.sync.aligned.m8n8.x4.shared.b16 {%0,%1,%2,%3}, [%4];" \
                 : "=r"(r0), "=r"(r1), "=r"(r2), "=r"(r3) : "r"(addr))
#define LDM_X4T(r0, r1, r2, r3, addr) \
    asm volatile("ldmatrix.sync.aligned.m8n8.x4.trans.shared.b16 {%0,%1,%2,%3}, [%4];" \
                 : "=r"(r0), "=r"(r1), "=r"(r2), "=r"(r3) : "r"(addr))

__device__ __forceinline__ float gelu_exact(float x) {
    return 0.5f * x * (1.0f + erff(x * 0.70710678118654752f));
}

// ------------------------------ convert kernel -----------------------------
__global__ void cvt_kernel(const float4* __restrict__ src, __half2* __restrict__ dst,
                           int n4) {
    int i = blockIdx.x * blockDim.x + threadIdx.x;
    if (i < n4) {
        float4 v = src[i];
        dst[2 * i]     = __floats2half2_rn(v.x, v.y);
        dst[2 * i + 1] = __floats2half2_rn(v.z, v.w);
    }
}

// ------------------------------ zero kernel --------------------------------
__global__ void zero_kernel(float* __restrict__ out) {
    int i = blockIdx.x * blockDim.x + threadIdx.x;
    if (i < T_TOK * H_DIM) out[i] = 0.0f;
    if (i < N_EXP) g_cnt[i] = 0;
}

// ------------------------------ router kernel ------------------------------
__global__ void router_kernel(const float* __restrict__ x,
                              const float* __restrict__ rw,
                              const float* __restrict__ rb) {
    int gwarp = (blockIdx.x * blockDim.x + threadIdx.x) >> 5;
    if (gwarp >= T_TOK) return;
    int lane = threadIdx.x & 31;
    const float* xr = x + (size_t)gwarp * H_DIM;
    float p[N_EXP];
#pragma unroll
    for (int e = 0; e < N_EXP; e++) p[e] = 0.0f;
    for (int i = lane; i < H_DIM; i += 32) {
        float xv = xr[i];
        const float4* r4 = (const float4*)(rw + i * N_EXP);
        float4 ra = r4[0], rc = r4[1];
        p[0] += xv * ra.x; p[1] += xv * ra.y; p[2] += xv * ra.z; p[3] += xv * ra.w;
        p[4] += xv * rc.x; p[5] += xv * rc.y; p[6] += xv * rc.z; p[7] += xv * rc.w;
    }
#pragma unroll
    for (int e = 0; e < N_EXP; e++) {
#pragma unroll
        for (int o = 16; o > 0; o >>= 1) p[e] += __shfl_xor_sync(0xffffffffu, p[e], o);
    }
    if (lane == 0) {
#pragma unroll
        for (int e = 0; e < N_EXP; e++) p[e] += rb[e];
        int i1 = 0;
#pragma unroll
        for (int e = 1; e < N_EXP; e++) if (p[e] > p[i1]) i1 = e;
        int i2 = (i1 == 0) ? 1 : 0;
#pragma unroll
        for (int e = 0; e < N_EXP; e++) if (e != i1 && p[e] > p[i2]) i2 = e;
        float wa = 1.0f / (1.0f + expf(p[i2] - p[i1]));
        float wb = 1.0f - wa;
        int p1 = atomicAdd(&g_cnt[i1], 1);
        g_list[i1][p1] = gwarp; g_wt[i1][p1] = wa;
        int p2 = atomicAdd(&g_cnt[i2], 1);
        g_list[i2][p2] = gwarp; g_wt[i2][p2] = wb;
    }
}

// --------------------------- grouped GEMM kernel ---------------------------
// A smem: [m(128)][k(32)] fp16, 64B rows, unit swizzle u^=(row&3).
// B smem: [k(32)][n(256)] fp16, 512B rows, unit swizzle u^=(k&7).
template <int KDIM, int NDIM, int PHASE>
__global__ void __launch_bounds__(NTHREADS)
moe_gemm(const __half* __restrict__ Ah,
         const __half* __restrict__ Wh,
         const float* __restrict__ bias,
         float* __restrict__ out) {
    extern __shared__ char smem[];
    const int e   = blockIdx.z;
    const int cnt = g_cnt[e];
    const int m0  = blockIdx.x * 128;
    if (m0 >= cnt) return;
    const int n0  = blockIdx.y * NT;

    const int tid  = threadIdx.x;
    const int lane = tid & 31;
    const int warp = tid >> 5;
    const int wm   = (warp & 3) * 32;    // 4 m-warps
    const int wn   = (warp >> 2) * 64;   // 4 n-warps
    const int grp  = lane >> 2;
    const int tig  = lane & 3;

    int*   sTok = (int*)(smem);          // [128]
    float* sWt  = (float*)(smem + 512);  // [128]

    if (tid < 128) {
        int mc = min(m0 + tid, cnt - 1);
        sTok[tid] = g_list[e][mc];
        sWt[tid]  = g_wt[e][mc];
    }
    __syncthreads();

    const __half* Aexp = (PHASE == 1) ? Ah : (g_h + (size_t)e * T_TOK * F_DIM);
    const __half* Wexp = Wh + (size_t)e * KDIM * NDIM;
    constexpr int NC = KDIM / KC;
    const uint32_t sb = smem_u32(smem) + SMEM_TILES_OFF;

    auto issue = [&](int c) {
        const uint32_t aB = sb + (c % NSTAGE) * STAGE_STRIDE;
        const uint32_t bB = aB + A_STAGE_BYTES;
        const int k0 = c * KC;
        // A tile: 512 16B-chunks, 1 per thread
        {
            int r = tid >> 2;
            int u = tid & 3;
            const __half* src;
            if (PHASE == 1) src = Ah + (size_t)sTok[r] * KDIM + k0 + u * 8;
            else            src = Aexp + (size_t)min(m0 + r, cnt - 1) * KDIM + k0 + u * 8;
            cp16(aB + (uint32_t)(r * 64 + ((u ^ (r & 3)) << 4)), src);
        }
        // B tile: 1024 16B-chunks, 2 per thread
#pragma unroll
        for (int i = 0; i < 2; i++) {
            int idx = tid + i * NTHREADS;
            int k   = idx >> 5;
            int u   = idx & 31;
            const __half* src = Wexp + (size_t)(k0 + k) * NDIM + n0 + u * 8;
            cp16(bB + (uint32_t)(k * 512 + ((u ^ (k & 7)) << 4)), src);
        }
        CP_COMMIT();
    };

    float acc[2][8][4];
#pragma unroll
    for (int mi = 0; mi < 2; mi++)
#pragma unroll
        for (int ni = 0; ni < 8; ni++)
#pragma unroll
            for (int q = 0; q < 4; q++) acc[mi][ni][q] = 0.0f;

    // per-lane ldmatrix coordinates
    const int l7 = lane & 7;
    const int lh = (lane >> 3) & 1;
    const int lu = lane >> 4;
    int aRow[2], aRx[2];
#pragma unroll
    for (int mi = 0; mi < 2; mi++) {
        int row = wm + mi * 16 + l7 + lh * 8;
        aRow[mi] = row * 64;
        aRx[mi]  = row & 3;
    }
    const int bUbase = (wn >> 3) + lu;

    // pipeline: prefetch depth NSTAGE-2; compute c = cc - (NSTAGE-2) for c in [0, NC)
#pragma unroll 1
    for (int cc = 0; cc < NC + NSTAGE - 2; cc++) {
        if (cc < NC) { issue(cc); } else { CP_COMMIT(); }
        if (cc < NSTAGE - 2) continue;
        const int c = cc - (NSTAGE - 2);
        asm volatile("cp.async.wait_group %0;" :: "n"(NSTAGE - 2) : "memory");
        __syncthreads();

        const uint32_t aB = sb + (c % NSTAGE) * STAGE_STRIDE;
        const uint32_t bB = aB + A_STAGE_BYTES;
#pragma unroll
        for (int ks = 0; ks < 2; ks++) {
            const int kl = ks * 16 + l7 + lh * 8;   // B k-row for this lane
            const uint32_t bkBase = bB + (uint32_t)(kl * 512);
            const int kx = kl & 7;
            uint32_t b0[8], b1[8];
#pragma unroll
            for (int pr = 0; pr < 4; pr++) {
                uint32_t addr = bkBase + (uint32_t)(((bUbase + pr * 2) ^ kx) << 4);
                LDM_X4T(b0[pr * 2], b1[pr * 2], b0[pr * 2 + 1], b1[pr * 2 + 1], addr);
            }
            uint32_t a[2][4];
#pragma unroll
            for (int mi = 0; mi < 2; mi++) {
                uint32_t addr = aB + (uint32_t)(aRow[mi] + (((ks * 2 + lu) ^ aRx[mi]) << 4));
                LDM_X4(a[mi][0], a[mi][1], a[mi][2], a[mi][3], addr);
            }
#pragma unroll
            for (int mi = 0; mi < 2; mi++)
#pragma unroll
                for (int ni = 0; ni < 8; ni++)
                    mma_f16(acc[mi][ni], a[mi], b0[ni], b1[ni]);
        }
    }
    asm volatile("cp.async.wait_group 0;" ::: "memory");

    // ------------------------------ epilogue ------------------------------
#pragma unroll
    for (int mi = 0; mi < 2; mi++) {
#pragma unroll
        for (int ni = 0; ni < 8; ni++) {
            int gn = n0 + wn + ni * 8 + tig * 2;
            float bv0 = bias[(size_t)e * NDIM + gn];
            float bv1 = bias[(size_t)e * NDIM + gn + 1];
#pragma unroll
            for (int half = 0; half < 2; half++) {
                int r = m0 + wm + mi * 16 + grp + half * 8;
                if (r < cnt) {
                    float v0 = acc[mi][ni][half * 2 + 0] + bv0;
                    float v1 = acc[mi][ni][half * 2 + 1] + bv1;
                    if (PHASE == 1) {
                        __half2* dst = (__half2*)(g_h + (size_t)e * T_TOK * F_DIM +
                                                  (size_t)r * F_DIM + gn);
                        *dst = __floats2half2_rn(gelu_exact(v0), gelu_exact(v1));
                    } else {
                        int   tok = sTok[r - m0];
                        float wt  = sWt[r - m0];
                        atomicAdd(&out[(size_t)tok * H_DIM + gn],     wt * v0);
                        atomicAdd(&out[(size_t)tok * H_DIM + gn + 1], wt * v1);
                    }
                }
            }
        }
    }
}

// ------------------------------ launch ------------------------------------
extern "C" void kernel_launch(void* const* d_in, const int* in_sizes, int n_in,
                              void* d_out, int out_size) {
    const float* x  = (const float*)d_in[0];
    const float* rw = (const float*)d_in[1];
    const float* rb = (const float*)d_in[2];
    const float* w1 = (const float*)d_in[3];
    const float* b1 = (const float*)d_in[4];
    const float* w2 = (const float*)d_in[5];
    const float* b2 = (const float*)d_in[6];
    float* out = (float*)d_out;

    cudaFuncSetAttribute(moe_gemm<H_DIM, F_DIM, 1>,
                         cudaFuncAttributeMaxDynamicSharedMemorySize, SMEM_BYTES);
    cudaFuncSetAttribute(moe_gemm<F_DIM, H_DIM, 2>,
                         cudaFuncAttributeMaxDynamicSharedMemorySize, SMEM_BYTES);

    __half *p_xh, *p_w1h, *p_w2h;
    cudaGetSymbolAddress((void**)&p_xh,  g_xh);
    cudaGetSymbolAddress((void**)&p_w1h, g_w1h);
    cudaGetSymbolAddress((void**)&p_w2h, g_w2h);

    const int n4_x  = T_TOK * H_DIM / 4;
    const int n4_w1 = N_EXP * H_DIM * F_DIM / 4;
    const int n4_w2 = N_EXP * F_DIM * H_DIM / 4;

    zero_kernel<<<(T_TOK * H_DIM + 255) / 256, 256>>>(out);
    cvt_kernel<<<(n4_x + 255) / 256, 256>>>((const float4*)x, (__half2*)p_xh, n4_x);
    cvt_kernel<<<(n4_w1 + 255) / 256, 256>>>((const float4*)w1, (__half2*)p_w1h, n4_w1);
    cvt_kernel<<<(n4_w2 + 255) / 256, 256>>>((const float4*)w2, (__half2*)p_w2h, n4_w2);
    router_kernel<<<(T_TOK * 32 + 255) / 256, 256>>>(x, rw, rb);
    moe_gemm<H_DIM, F_DIM, 1>
        <<<dim3(T_TOK / 128, F_DIM / NT, N_EXP), NTHREADS, SMEM_BYTES>>>(p_xh, p_w1h, b1, nullptr);
    moe_gemm<F_DIM, H_DIM, 2>
        <<<dim3(T_TOK / 128, H_DIM / NT, N_EXP), NTHREADS, SMEM_BYTES>>>(nullptr, p_w2h, b2, out);
}

// round 11
// speedup vs baseline: 1.2186x; 1.1778x over previous
#include <cuda_runtime.h>
#include <cuda_fp16.h>
#include <cstdint>

// Problem constants
#define T_TOK 4096
#define H_DIM 1024
#define F_DIM 4096
#define N_EXP 8

// Tiling: CTA 128m x 256n x 64k, 16 warps (4m x 4n), warp tile 32x64, fp16 MMA
#define NT 256
#define KC 64
#define NTHREADS 512
#define NSTAGE 4
#define A_STAGE_BYTES (128 * 128)         // 128 rows x 64 halves (128B)
#define B_STAGE_BYTES (KC * NT * 2)       // 64 k-rows x 512B
#define STAGE_STRIDE  (A_STAGE_BYTES + B_STAGE_BYTES)   // 48KB
#define SMEM_TILES_OFF 1024
#define SMEM_BYTES (SMEM_TILES_OFF + NSTAGE * STAGE_STRIDE)   // 197632

// -------- device scratch --------
__device__ int    g_cnt[N_EXP];
__device__ int    g_list[N_EXP][T_TOK];
__device__ int    g_dst[N_EXP][T_TOK];     // tok*2 + slot (dense output slot)
__device__ float  g_wt[N_EXP][T_TOK];
__device__ __half g_xh[(size_t)T_TOK * H_DIM];
__device__ __half g_w1h[(size_t)N_EXP * H_DIM * F_DIM];
__device__ __half g_w2h[(size_t)N_EXP * F_DIM * H_DIM];
__device__ __half g_h[(size_t)N_EXP * T_TOK * F_DIM];
__device__ float  g_y[(size_t)T_TOK * 2 * H_DIM];   // per-slot weighted expert outputs

// -------- helpers --------
__device__ __forceinline__ uint32_t smem_u32(const void* p) {
    uint32_t a;
    asm("{ .reg .u64 t; cvta.to.shared.u64 t, %1; cvt.u32.u64 %0, t; }" : "=r"(a) : "l"(p));
    return a;
}
__device__ __forceinline__ void cp16(uint32_t dst, const void* src) {
    asm volatile("cp.async.cg.shared.global [%0], [%1], 16;" :: "r"(dst), "l"(src) : "memory");
}
#define CP_COMMIT() asm volatile("cp.async.commit_group;" ::: "memory")

__device__ __forceinline__ void mma_f16(float c[4], const uint32_t a[4],
                                        uint32_t b0, uint32_t b1) {
    asm volatile(
        "mma.sync.aligned.m16n8k16.row.col.f32.f16.f16.f32 "
        "{%0,%1,%2,%3}, {%4,%5,%6,%7}, {%8,%9}, {%0,%1,%2,%3};"
        : "+f"(c[0]), "+f"(c[1]), "+f"(c[2]), "+f"(c[3])
        : "r"(a[0]), "r"(a[1]), "r"(a[2]), "r"(a[3]), "r"(b0), "r"(b1));
}
#define LDM_X4(r0, r1, r2, r3, addr) \
    asm volatile("ldmatrix.sync.aligned.m8n8.x4.shared.b16 {%0,%1,%2,%3}, [%4];" \
                 : "=r"(r0), "=r"(r1), "=r"(r2), "=r"(r3) : "r"(addr))
#define LDM_X4T(r0, r1, r2, r3, addr) \
    asm volatile("ldmatrix.sync.aligned.m8n8.x4.trans.shared.b16 {%0,%1,%2,%3}, [%4];" \
                 : "=r"(r0), "=r"(r1), "=r"(r2), "=r"(r3) : "r"(addr))

__device__ __forceinline__ float gelu_exact(float x) {
    return 0.5f * x * (1.0f + erff(x * 0.70710678118654752f));
}

// ------------------------------ convert kernel -----------------------------
__global__ void cvt_kernel(const float4* __restrict__ src, __half2* __restrict__ dst,
                           int n4) {
    int i = blockIdx.x * blockDim.x + threadIdx.x;
    if (i < n4) {
        float4 v = src[i];
        dst[2 * i]     = __floats2half2_rn(v.x, v.y);
        dst[2 * i + 1] = __floats2half2_rn(v.z, v.w);
    }
}

// ------------------------------ counter zero kernel ------------------------
__global__ void zero_cnt_kernel() {
    if (threadIdx.x < N_EXP) g_cnt[threadIdx.x] = 0;
}

// ------------- router kernel (also converts x -> fp16) ---------------------
__global__ void router_kernel(const float* __restrict__ x,
                              const float* __restrict__ rw,
                              const float* __restrict__ rb) {
    int t = (blockIdx.x * blockDim.x + threadIdx.x) >> 5;
    if (t >= T_TOK) return;
    int lane = threadIdx.x & 31;
    const float4* xr4 = (const float4*)(x + (size_t)t * H_DIM);
    __half2* xh2 = (__half2*)(g_xh + (size_t)t * H_DIM);

    float p[N_EXP];
#pragma unroll
    for (int e = 0; e < N_EXP; e++) p[e] = 0.0f;

    for (int i4 = lane; i4 < H_DIM / 4; i4 += 32) {
        float4 v = xr4[i4];
        int h = i4 * 4;
        // write fp16 copy of x
        xh2[i4 * 2]     = __floats2half2_rn(v.x, v.y);
        xh2[i4 * 2 + 1] = __floats2half2_rn(v.z, v.w);
        const float* vv = &v.x;
#pragma unroll
        for (int j = 0; j < 4; j++) {
            const float4* r4 = (const float4*)(rw + (size_t)(h + j) * N_EXP);
            float4 ra = r4[0], rc = r4[1];
            float xv = vv[j];
            p[0] += xv * ra.x; p[1] += xv * ra.y; p[2] += xv * ra.z; p[3] += xv * ra.w;
            p[4] += xv * rc.x; p[5] += xv * rc.y; p[6] += xv * rc.z; p[7] += xv * rc.w;
        }
    }
#pragma unroll
    for (int e = 0; e < N_EXP; e++) {
#pragma unroll
        for (int o = 16; o > 0; o >>= 1) p[e] += __shfl_xor_sync(0xffffffffu, p[e], o);
    }
    if (lane == 0) {
#pragma unroll
        for (int e = 0; e < N_EXP; e++) p[e] += rb[e];
        int i1 = 0;
#pragma unroll
        for (int e = 1; e < N_EXP; e++) if (p[e] > p[i1]) i1 = e;
        int i2 = (i1 == 0) ? 1 : 0;
#pragma unroll
        for (int e = 0; e < N_EXP; e++) if (e != i1 && p[e] > p[i2]) i2 = e;
        float wa = 1.0f / (1.0f + expf(p[i2] - p[i1]));
        float wb = 1.0f - wa;
        int p1 = atomicAdd(&g_cnt[i1], 1);
        g_list[i1][p1] = t; g_wt[i1][p1] = wa; g_dst[i1][p1] = t * 2;
        int p2 = atomicAdd(&g_cnt[i2], 1);
        g_list[i2][p2] = t; g_wt[i2][p2] = wb; g_dst[i2][p2] = t * 2 + 1;
    }
}

// ------------------------------ combine kernel -----------------------------
__global__ void combine_kernel(float4* __restrict__ out) {
    int i = blockIdx.x * blockDim.x + threadIdx.x;
    if (i >= T_TOK * H_DIM / 4) return;
    int t = i >> 8;              // H_DIM/4 = 256 float4 per token
    int rest = i & 255;
    const float4* y4 = (const float4*)g_y;
    float4 a = y4[((size_t)(t * 2) << 8) | rest];
    float4 b = y4[((size_t)(t * 2 + 1) << 8) | rest];
    out[i] = make_float4(a.x + b.x, a.y + b.y, a.z + b.z, a.w + b.w);
}

// --------------------------- grouped GEMM kernel ---------------------------
// A smem: [m(128)][k(64)] fp16, 128B rows, unit swizzle u^=(row&7).
// B smem: [k(64)][n(256)] fp16, 512B rows, unit swizzle u^=(k&7).
template <int KDIM, int NDIM, int PHASE>
__global__ void __launch_bounds__(NTHREADS)
moe_gemm(const __half* __restrict__ Ah,
         const __half* __restrict__ Wh,
         const float* __restrict__ bias,
         float* __restrict__ out) {
    extern __shared__ char smem[];
    const int e   = blockIdx.z;
    const int cnt = g_cnt[e];
    const int m0  = blockIdx.x * 128;
    if (m0 >= cnt) return;
    const int n0  = blockIdx.y * NT;

    const int tid  = threadIdx.x;
    const int lane = tid & 31;
    const int warp = tid >> 5;
    const int wm   = (warp & 3) * 32;    // 4 m-warps
    const int wn   = (warp >> 2) * 64;   // 4 n-warps
    const int grp  = lane >> 2;
    const int tig  = lane & 3;

    int*   sTok = (int*)(smem);          // [128]
    float* sWt  = (float*)(smem + 512);  // [128]
    int*   sDst = (int*)(smem + 1024 - 512 + 512);  // reuse: place at smem+? see below
    // layout: sTok [0,512), sWt [512,1024) -- sDst overlaps tiles region start? No:
    // put sDst in the first 512B of the tiles area is unsafe; instead pack into header:
    // header is 1024B; we need 128*4*3 = 1536B. Extend header usage into stage area is
    // wrong, so store dst in registers via reload below instead.

    if (tid < 128) {
        int mc = min(m0 + tid, cnt - 1);
        sTok[tid] = g_list[e][mc];
        sWt[tid]  = g_wt[e][mc];
    }
    __syncthreads();

    const __half* Aexp = (PHASE == 1) ? Ah : (g_h + (size_t)e * T_TOK * F_DIM);
    const __half* Wexp = Wh + (size_t)e * KDIM * NDIM;
    constexpr int NC = KDIM / KC;
    const uint32_t sb = smem_u32(smem) + SMEM_TILES_OFF;

    auto issue = [&](int c) {
        const uint32_t aB = sb + (c % NSTAGE) * STAGE_STRIDE;
        const uint32_t bB = aB + A_STAGE_BYTES;
        const int k0 = c * KC;
        // A tile: 128 rows x 8 units = 1024 chunks, 2 per thread
#pragma unroll
        for (int i = 0; i < 2; i++) {
            int idx = tid + i * NTHREADS;
            int r   = idx >> 3;
            int u   = idx & 7;
            const __half* src;
            if (PHASE == 1) src = Ah + (size_t)sTok[r] * KDIM + k0 + u * 8;
            else            src = Aexp + (size_t)min(m0 + r, cnt - 1) * KDIM + k0 + u * 8;
            cp16(aB + (uint32_t)(r * 128 + ((u ^ (r & 7)) << 4)), src);
        }
        // B tile: 64 k-rows x 32 units = 2048 chunks, 4 per thread
#pragma unroll
        for (int i = 0; i < 4; i++) {
            int idx = tid + i * NTHREADS;
            int k   = idx >> 5;
            int u   = idx & 31;
            const __half* src = Wexp + (size_t)(k0 + k) * NDIM + n0 + u * 8;
            cp16(bB + (uint32_t)(k * 512 + ((u ^ (k & 7)) << 4)), src);
        }
        CP_COMMIT();
    };

    float acc[2][8][4];
#pragma unroll
    for (int mi = 0; mi < 2; mi++)
#pragma unroll
        for (int ni = 0; ni < 8; ni++)
#pragma unroll
            for (int q = 0; q < 4; q++) acc[mi][ni][q] = 0.0f;

    // per-lane ldmatrix coordinates
    const int l7 = lane & 7;
    const int lh = (lane >> 3) & 1;
    const int lu = lane >> 4;
    int aRow[2], aRx[2];
#pragma unroll
    for (int mi = 0; mi < 2; mi++) {
        int row = wm + mi * 16 + l7 + lh * 8;
        aRow[mi] = row * 128;
        aRx[mi]  = row & 7;
    }
    const int bUbase = (wn >> 3) + lu;

    // pipeline: prefetch depth NSTAGE-2; compute c = cc - (NSTAGE-2) for c in [0, NC)
#pragma unroll 1
    for (int cc = 0; cc < NC + NSTAGE - 2; cc++) {
        if (cc < NC) { issue(cc); } else { CP_COMMIT(); }
        if (cc < NSTAGE - 2) continue;
        const int c = cc - (NSTAGE - 2);
        asm volatile("cp.async.wait_group %0;" :: "n"(NSTAGE - 2) : "memory");
        __syncthreads();

        const uint32_t aB = sb + (c % NSTAGE) * STAGE_STRIDE;
        const uint32_t bB = aB + A_STAGE_BYTES;
#pragma unroll
        for (int ks = 0; ks < 4; ks++) {
            const int kl = ks * 16 + l7 + lh * 8;   // B k-row for this lane (0..63)
            const uint32_t bkBase = bB + (uint32_t)(kl * 512);
            const int kx = kl & 7;
            uint32_t b0[8], b1[8];
#pragma unroll
            for (int pr = 0; pr < 4; pr++) {
                uint32_t addr = bkBase + (uint32_t)(((bUbase + pr * 2) ^ kx) << 4);
                LDM_X4T(b0[pr * 2], b1[pr * 2], b0[pr * 2 + 1], b1[pr * 2 + 1], addr);
            }
            uint32_t a[2][4];
#pragma unroll
            for (int mi = 0; mi < 2; mi++) {
                uint32_t addr = aB + (uint32_t)(aRow[mi] + (((ks * 2 + lu) ^ aRx[mi]) << 4));
                LDM_X4(a[mi][0], a[mi][1], a[mi][2], a[mi][3], addr);
            }
#pragma unroll
            for (int mi = 0; mi < 2; mi++)
#pragma unroll
                for (int ni = 0; ni < 8; ni++)
                    mma_f16(acc[mi][ni], a[mi], b0[ni], b1[ni]);
        }
    }
    asm volatile("cp.async.wait_group 0;" ::: "memory");

    // ------------------------------ epilogue ------------------------------
#pragma unroll
    for (int mi = 0; mi < 2; mi++) {
#pragma unroll
        for (int ni = 0; ni < 8; ni++) {
            int gn = n0 + wn + ni * 8 + tig * 2;
            float bv0 = bias[(size_t)e * NDIM + gn];
            float bv1 = bias[(size_t)e * NDIM + gn + 1];
#pragma unroll
            for (int half = 0; half < 2; half++) {
                int r = m0 + wm + mi * 16 + grp + half * 8;
                if (r < cnt) {
                    float v0 = acc[mi][ni][half * 2 + 0] + bv0;
                    float v1 = acc[mi][ni][half * 2 + 1] + bv1;
                    if (PHASE == 1) {
                        __half2* dst = (__half2*)(g_h + (size_t)e * T_TOK * F_DIM +
                                                  (size_t)r * F_DIM + gn);
                        *dst = __floats2half2_rn(gelu_exact(v0), gelu_exact(v1));
                    } else {
                        int   d  = g_dst[e][r];
                        float wt = sWt[r - m0];
                        float2* op = (float2*)(g_y + (size_t)d * H_DIM + gn);
                        *op = make_float2(wt * v0, wt * v1);
                    }
                }
            }
        }
    }
}

// ------------------------------ launch ------------------------------------
extern "C" void kernel_launch(void* const* d_in, const int* in_sizes, int n_in,
                              void* d_out, int out_size) {
    const float* x  = (const float*)d_in[0];
    const float* rw = (const float*)d_in[1];
    const float* rb = (const float*)d_in[2];
    const float* w1 = (const float*)d_in[3];
    const float* b1 = (const float*)d_in[4];
    const float* w2 = (const float*)d_in[5];
    const float* b2 = (const float*)d_in[6];
    float* out = (float*)d_out;

    cudaFuncSetAttribute(moe_gemm<H_DIM, F_DIM, 1>,
                         cudaFuncAttributeMaxDynamicSharedMemorySize, SMEM_BYTES);
    cudaFuncSetAttribute(moe_gemm<F_DIM, H_DIM, 2>,
                         cudaFuncAttributeMaxDynamicSharedMemorySize, SMEM_BYTES);

    __half *p_w1h, *p_w2h, *p_xh;
    cudaGetSymbolAddress((void**)&p_xh,  g_xh);
    cudaGetSymbolAddress((void**)&p_w1h, g_w1h);
    cudaGetSymbolAddress((void**)&p_w2h, g_w2h);

    const int n4_w1 = N_EXP * H_DIM * F_DIM / 4;
    const int n4_w2 = N_EXP * F_DIM * H_DIM / 4;

    zero_cnt_kernel<<<1, 32>>>();
    cvt_kernel<<<(n4_w1 + 255) / 256, 256>>>((const float4*)w1, (__half2*)p_w1h, n4_w1);
    cvt_kernel<<<(n4_w2 + 255) / 256, 256>>>((const float4*)w2, (__half2*)p_w2h, n4_w2);
    router_kernel<<<(T_TOK * 32 + 255) / 256, 256>>>(x, rw, rb);
    moe_gemm<H_DIM, F_DIM, 1>
        <<<dim3(T_TOK / 128, F_DIM / NT, N_EXP), NTHREADS, SMEM_BYTES>>>(p_xh, p_w1h, b1, nullptr);
    moe_gemm<F_DIM, H_DIM, 2>
        <<<dim3(T_TOK / 128, H_DIM / NT, N_EXP), NTHREADS, SMEM_BYTES>>>(nullptr, p_w2h, b2, nullptr);
    combine_kernel<<<(T_TOK * H_DIM / 4 + 255) / 256, 256>>>((float4*)out);
}

// round 17
// speedup vs baseline: 1.2707x; 1.0428x over previous
#include <cuda_runtime.h>
#include <cuda_fp16.h>
#include <cstdint>

// Problem constants
#define T_TOK 4096
#define H_DIM 1024
#define F_DIM 4096
#define N_EXP 8

// Tiling: CTA 128m x 256n x 64k, 16 warps (4m x 4n), warp tile 32x64, fp16 MMA
#define NT 256
#define KC 64
#define NTHREADS 512
#define NSTAGE 4
#define A_STAGE_BYTES (128 * 128)         // 128 rows x 64 halves (128B)
#define B_STAGE_BYTES (KC * NT * 2)       // 64 k-rows x 512B
#define STAGE_STRIDE  (A_STAGE_BYTES + B_STAGE_BYTES)   // 48KB
#define SMEM_TILES_OFF 1024
#define SMEM_BYTES (SMEM_TILES_OFF + NSTAGE * STAGE_STRIDE)   // 197632

// -------- device scratch --------
__device__ int    g_cnt[N_EXP];
__device__ int    g_list[N_EXP][T_TOK];
__device__ int    g_dst[N_EXP][T_TOK];     // tok*2 + slot (dense output slot)
__device__ float  g_wt[N_EXP][T_TOK];
__device__ float  g_rwT[N_EXP * H_DIM];    // transposed router weights [e][h]
__device__ __half g_xh[(size_t)T_TOK * H_DIM];
__device__ __half g_w1h[(size_t)N_EXP * H_DIM * F_DIM];
__device__ __half g_w2h[(size_t)N_EXP * F_DIM * H_DIM];
__device__ __half g_h[(size_t)N_EXP * T_TOK * F_DIM];
__device__ float  g_y[(size_t)T_TOK * 2 * H_DIM];   // per-slot weighted expert outputs

// -------- helpers --------
__device__ __forceinline__ uint32_t h2_bits(__half2 h) {
    return *reinterpret_cast<uint32_t*>(&h);
}
__device__ __forceinline__ uint32_t smem_u32(const void* p) {
    uint32_t a;
    asm("{ .reg .u64 t; cvta.to.shared.u64 t, %1; cvt.u32.u64 %0, t; }" : "=r"(a) : "l"(p));
    return a;
}
__device__ __forceinline__ void cp16(uint32_t dst, const void* src) {
    asm volatile("cp.async.cg.shared.global [%0], [%1], 16;" :: "r"(dst), "l"(src) : "memory");
}
#define CP_COMMIT() asm volatile("cp.async.commit_group;" ::: "memory")

__device__ __forceinline__ void mma_f16(float c[4], const uint32_t a[4],
                                        uint32_t b0, uint32_t b1) {
    asm volatile(
        "mma.sync.aligned.m16n8k16.row.col.f32.f16.f16.f32 "
        "{%0,%1,%2,%3}, {%4,%5,%6,%7}, {%8,%9}, {%0,%1,%2,%3};"
        : "+f"(c[0]), "+f"(c[1]), "+f"(c[2]), "+f"(c[3])
        : "r"(a[0]), "r"(a[1]), "r"(a[2]), "r"(a[3]), "r"(b0), "r"(b1));
}
#define LDM_X4(r0, r1, r2, r3, addr) \
    asm volatile("ldmatrix.sync.aligned.m8n8.x4.shared.b16 {%0,%1,%2,%3}, [%4];" \
                 : "=r"(r0), "=r"(r1), "=r"(r2), "=r"(r3) : "r"(addr))
#define LDM_X4T(r0, r1, r2, r3, addr) \
    asm volatile("ldmatrix.sync.aligned.m8n8.x4.trans.shared.b16 {%0,%1,%2,%3}, [%4];" \
                 : "=r"(r0), "=r"(r1), "=r"(r2), "=r"(r3) : "r"(addr))

__device__ __forceinline__ float gelu_exact(float x) {
    return 0.5f * x * (1.0f + erff(x * 0.70710678118654752f));
}

// -------------------- prep kernel: counters + rw transpose -----------------
__global__ void prep_kernel(const float* __restrict__ rw) {
    int i = blockIdx.x * blockDim.x + threadIdx.x;
    if (i < N_EXP) g_cnt[i] = 0;
    if (i < H_DIM * N_EXP) {
        int h = i >> 3, e = i & 7;
        g_rwT[e * H_DIM + h] = rw[i];
    }
}

// ------------------------------ convert kernel -----------------------------
// 32B per thread: 2 x LDG.128 -> 1 x STG.128 of halves
__global__ void cvt_kernel(const float4* __restrict__ src, uint4* __restrict__ dst,
                           int n8) {
    int i = blockIdx.x * blockDim.x + threadIdx.x;
    if (i < n8) {
        float4 a = src[2 * i];
        float4 b = src[2 * i + 1];
        uint4 o;
        o.x = h2_bits(__floats2half2_rn(a.x, a.y));
        o.y = h2_bits(__floats2half2_rn(a.z, a.w));
        o.z = h2_bits(__floats2half2_rn(b.x, b.y));
        o.w = h2_bits(__floats2half2_rn(b.z, b.w));
        dst[i] = o;
    }
}

// ------------- router kernel (coalesced rwT; also converts x -> fp16) ------
__global__ void router_kernel(const float* __restrict__ x,
                              const float* __restrict__ rb) {
    int t = (blockIdx.x * blockDim.x + threadIdx.x) >> 5;
    if (t >= T_TOK) return;
    int lane = threadIdx.x & 31;
    const float4* xr4 = (const float4*)(x + (size_t)t * H_DIM);
    const float4* rwT4 = (const float4*)g_rwT;
    __half2* xh2 = (__half2*)(g_xh + (size_t)t * H_DIM);

    float p[N_EXP];
#pragma unroll
    for (int e = 0; e < N_EXP; e++) p[e] = 0.0f;

    for (int i4 = lane; i4 < H_DIM / 4; i4 += 32) {
        float4 v = xr4[i4];
        xh2[i4 * 2]     = __floats2half2_rn(v.x, v.y);
        xh2[i4 * 2 + 1] = __floats2half2_rn(v.z, v.w);
#pragma unroll
        for (int e = 0; e < N_EXP; e++) {
            float4 r = rwT4[e * (H_DIM / 4) + i4];   // coalesced across lanes
            p[e] += v.x * r.x + v.y * r.y + v.z * r.z + v.w * r.w;
        }
    }
#pragma unroll
    for (int e = 0; e < N_EXP; e++) {
#pragma unroll
        for (int o = 16; o > 0; o >>= 1) p[e] += __shfl_xor_sync(0xffffffffu, p[e], o);
    }
    if (lane == 0) {
#pragma unroll
        for (int e = 0; e < N_EXP; e++) p[e] += rb[e];
        int i1 = 0;
#pragma unroll
        for (int e = 1; e < N_EXP; e++) if (p[e] > p[i1]) i1 = e;
        int i2 = (i1 == 0) ? 1 : 0;
#pragma unroll
        for (int e = 0; e < N_EXP; e++) if (e != i1 && p[e] > p[i2]) i2 = e;
        float wa = 1.0f / (1.0f + expf(p[i2] - p[i1]));
        float wb = 1.0f - wa;
        int p1 = atomicAdd(&g_cnt[i1], 1);
        g_list[i1][p1] = t; g_wt[i1][p1] = wa; g_dst[i1][p1] = t * 2;
        int p2 = atomicAdd(&g_cnt[i2], 1);
        g_list[i2][p2] = t; g_wt[i2][p2] = wb; g_dst[i2][p2] = t * 2 + 1;
    }
}

// ------------------------------ combine kernel -----------------------------
__global__ void combine_kernel(float4* __restrict__ out) {
    int i = blockIdx.x * blockDim.x + threadIdx.x;
    if (i >= T_TOK * H_DIM / 4) return;
    int t = i >> 8;              // H_DIM/4 = 256 float4 per token
    int rest = i & 255;
    const float4* y4 = (const float4*)g_y;
    float4 a = y4[((size_t)(t * 2) << 8) | rest];
    float4 b = y4[((size_t)(t * 2 + 1) << 8) | rest];
    out[i] = make_float4(a.x + b.x, a.y + b.y, a.z + b.z, a.w + b.w);
}

// --------------------------- grouped GEMM kernel ---------------------------
// A smem: [m(128)][k(64)] fp16, 128B rows, unit swizzle u^=(row&7).
// B smem: [k(64)][n(256)] fp16, 512B rows, unit swizzle u^=(k&7).
template <int KDIM, int NDIM, int PHASE>
__global__ void __launch_bounds__(NTHREADS)
moe_gemm(const __half* __restrict__ Ah,
         const __half* __restrict__ Wh,
         const float* __restrict__ bias,
         float* __restrict__ out) {
    extern __shared__ char smem[];
    const int e   = blockIdx.z;
    const int cnt = g_cnt[e];
    const int m0  = blockIdx.x * 128;
    if (m0 >= cnt) return;
    const int n0  = blockIdx.y * NT;

    const int tid  = threadIdx.x;
    const int lane = tid & 31;
    const int warp = tid >> 5;
    const int wm   = (warp & 3) * 32;    // 4 m-warps
    const int wn   = (warp >> 2) * 64;   // 4 n-warps
    const int grp  = lane >> 2;
    const int tig  = lane & 3;

    int*   sTok = (int*)(smem);          // [128]
    float* sWt  = (float*)(smem + 512);  // [128]

    if (tid < 128) {
        int mc = min(m0 + tid, cnt - 1);
        sTok[tid] = g_list[e][mc];
        sWt[tid]  = g_wt[e][mc];
    }
    __syncthreads();

    const __half* Aexp = (PHASE == 1) ? Ah : (g_h + (size_t)e * T_TOK * F_DIM);
    const __half* Wexp = Wh + (size_t)e * KDIM * NDIM;
    constexpr int NC = KDIM / KC;
    const uint32_t sb = smem_u32(smem) + SMEM_TILES_OFF;

    auto issue = [&](int c) {
        const uint32_t aB = sb + (c % NSTAGE) * STAGE_STRIDE;
        const uint32_t bB = aB + A_STAGE_BYTES;
        const int k0 = c * KC;
        // A tile: 128 rows x 8 units = 1024 chunks, 2 per thread
#pragma unroll
        for (int i = 0; i < 2; i++) {
            int idx = tid + i * NTHREADS;
            int r   = idx >> 3;
            int u   = idx & 7;
            const __half* src;
            if (PHASE == 1) src = Ah + (size_t)sTok[r] * KDIM + k0 + u * 8;
            else            src = Aexp + (size_t)min(m0 + r, cnt - 1) * KDIM + k0 + u * 8;
            cp16(aB + (uint32_t)(r * 128 + ((u ^ (r & 7)) << 4)), src);
        }
        // B tile: 64 k-rows x 32 units = 2048 chunks, 4 per thread
#pragma unroll
        for (int i = 0; i < 4; i++) {
            int idx = tid + i * NTHREADS;
            int k   = idx >> 5;
            int u   = idx & 31;
            const __half* src = Wexp + (size_t)(k0 + k) * NDIM + n0 + u * 8;
            cp16(bB + (uint32_t)(k * 512 + ((u ^ (k & 7)) << 4)), src);
        }
        CP_COMMIT();
    };

    float acc[2][8][4];
#pragma unroll
    for (int mi = 0; mi < 2; mi++)
#pragma unroll
        for (int ni = 0; ni < 8; ni++)
#pragma unroll
            for (int q = 0; q < 4; q++) acc[mi][ni][q] = 0.0f;

    // per-lane ldmatrix coordinates
    const int l7 = lane & 7;
    const int lh = (lane >> 3) & 1;
    const int lu = lane >> 4;
    int aRow[2], aRx[2];
#pragma unroll
    for (int mi = 0; mi < 2; mi++) {
        int row = wm + mi * 16 + l7 + lh * 8;
        aRow[mi] = row * 128;
        aRx[mi]  = row & 7;
    }
    const int bUbase = (wn >> 3) + lu;

    // pipeline: prefetch depth NSTAGE-2; compute c = cc - (NSTAGE-2) for c in [0, NC)
#pragma unroll 1
    for (int cc = 0; cc < NC + NSTAGE - 2; cc++) {
        if (cc < NC) { issue(cc); } else { CP_COMMIT(); }
        if (cc < NSTAGE - 2) continue;
        const int c = cc - (NSTAGE - 2);
        asm volatile("cp.async.wait_group %0;" :: "n"(NSTAGE - 2) : "memory");
        __syncthreads();

        const uint32_t aB = sb + (c % NSTAGE) * STAGE_STRIDE;
        const uint32_t bB = aB + A_STAGE_BYTES;
#pragma unroll
        for (int ks = 0; ks < 4; ks++) {
            const int kl = ks * 16 + l7 + lh * 8;   // B k-row for this lane (0..63)
            const uint32_t bkBase = bB + (uint32_t)(kl * 512);
            const int kx = kl & 7;
            uint32_t b0[8], b1[8];
#pragma unroll
            for (int pr = 0; pr < 4; pr++) {
                uint32_t addr = bkBase + (uint32_t)(((bUbase + pr * 2) ^ kx) << 4);
                LDM_X4T(b0[pr * 2], b1[pr * 2], b0[pr * 2 + 1], b1[pr * 2 + 1], addr);
            }
            uint32_t a[2][4];
#pragma unroll
            for (int mi = 0; mi < 2; mi++) {
                uint32_t addr = aB + (uint32_t)(aRow[mi] + (((ks * 2 + lu) ^ aRx[mi]) << 4));
                LDM_X4(a[mi][0], a[mi][1], a[mi][2], a[mi][3], addr);
            }
#pragma unroll
            for (int mi = 0; mi < 2; mi++)
#pragma unroll
                for (int ni = 0; ni < 8; ni++)
                    mma_f16(acc[mi][ni], a[mi], b0[ni], b1[ni]);
        }
    }
    asm volatile("cp.async.wait_group 0;" ::: "memory");

    // ------------------------------ epilogue ------------------------------
#pragma unroll
    for (int mi = 0; mi < 2; mi++) {
#pragma unroll
        for (int ni = 0; ni < 8; ni++) {
            int gn = n0 + wn + ni * 8 + tig * 2;
            float bv0 = bias[(size_t)e * NDIM + gn];
            float bv1 = bias[(size_t)e * NDIM + gn + 1];
#pragma unroll
            for (int half = 0; half < 2; half++) {
                int r = m0 + wm + mi * 16 + grp + half * 8;
                if (r < cnt) {
                    float v0 = acc[mi][ni][half * 2 + 0] + bv0;
                    float v1 = acc[mi][ni][half * 2 + 1] + bv1;
                    if (PHASE == 1) {
                        __half2* dst = (__half2*)(g_h + (size_t)e * T_TOK * F_DIM +
                                                  (size_t)r * F_DIM + gn);
                        *dst = __floats2half2_rn(gelu_exact(v0), gelu_exact(v1));
                    } else {
                        int   d  = g_dst[e][r];
                        float wt = sWt[r - m0];
                        float2* op = (float2*)(g_y + (size_t)d * H_DIM + gn);
                        *op = make_float2(wt * v0, wt * v1);
                    }
                }
            }
        }
    }
}

// ------------------------------ launch ------------------------------------
extern "C" void kernel_launch(void* const* d_in, const int* in_sizes, int n_in,
                              void* d_out, int out_size) {
    const float* x  = (const float*)d_in[0];
    const float* rw = (const float*)d_in[1];
    const float* rb = (const float*)d_in[2];
    const float* w1 = (const float*)d_in[3];
    const float* b1 = (const float*)d_in[4];
    const float* w2 = (const float*)d_in[5];
    const float* b2 = (const float*)d_in[6];
    float* out = (float*)d_out;

    cudaFuncSetAttribute(moe_gemm<H_DIM, F_DIM, 1>,
                         cudaFuncAttributeMaxDynamicSharedMemorySize, SMEM_BYTES);
    cudaFuncSetAttribute(moe_gemm<F_DIM, H_DIM, 2>,
                         cudaFuncAttributeMaxDynamicSharedMemorySize, SMEM_BYTES);

    __half *p_w1h, *p_w2h, *p_xh;
    cudaGetSymbolAddress((void**)&p_xh,  g_xh);
    cudaGetSymbolAddress((void**)&p_w1h, g_w1h);
    cudaGetSymbolAddress((void**)&p_w2h, g_w2h);

    const int n8_w1 = N_EXP * H_DIM * F_DIM / 8;
    const int n8_w2 = N_EXP * F_DIM * H_DIM / 8;

    prep_kernel<<<(H_DIM * N_EXP + 255) / 256, 256>>>(rw);
    cvt_kernel<<<(n8_w1 + 255) / 256, 256>>>((const float4*)w1, (uint4*)p_w1h, n8_w1);
    cvt_kernel<<<(n8_w2 + 255) / 256, 256>>>((const float4*)w2, (uint4*)p_w2h, n8_w2);
    router_kernel<<<(T_TOK * 32 + 255) / 256, 256>>>(x, rb);
    moe_gemm<H_DIM, F_DIM, 1>
        <<<dim3(T_TOK / 128, F_DIM / NT, N_EXP), NTHREADS, SMEM_BYTES>>>(p_xh, p_w1h, b1, nullptr);
    moe_gemm<F_DIM, H_DIM, 2>
        <<<dim3(T_TOK / 128, H_DIM / NT, N_EXP), NTHREADS, SMEM_BYTES>>>(nullptr, p_w2h, b2, nullptr);
    combine_kernel<<<(T_TOK * H_DIM / 4 + 255) / 256, 256>>>((float4*)out);
}